// round 3
// baseline (speedup 1.0000x reference)
#include <cuda_runtime.h>
#include <math.h>

#define LAM 1.0
#define NT 256

// Hosking / Levinson-Durbin recursion, all-fp32 data path.
// One CTA per batch. Covariance built in fp64 (real cancellation), recursion,
// dots, and sampling in fp32. 2 barriers per step; no serialized thread-0
// fp64 chains; cumsum + output deferred past the loop.
__global__ __launch_bounds__(NT, 1)
void fbm_hosking_f32(const float* __restrict__ alpha,
                     const float* __restrict__ tau,
                     const float* __restrict__ diffusion,
                     const float* __restrict__ du,
                     float* __restrict__ out,
                     int T)
{
    const int N = T - 1;                  // 1023
    extern __shared__ float sh[];
    float* r   = sh;                      // [N]    autocovariance (fp32)
    float* phi = r + N;                   // [N+1]  AR coefficients
    float* xh  = phi + (N + 1);           // [3*N]  increments per dim
    float* red = xh + 3 * N;              // [8*8]  per-warp partials (7 used)
    float* zsh = red + 64;                // [3*N]  staged noise

    const int b    = blockIdx.x;
    const int tid  = threadIdx.x;
    const int lane = tid & 31;
    const int warp = tid >> 5;

    const double a  = (double)alpha[b];
    const float  tb = tau[b];
    const float  sd = sqrtf(diffusion[b]);

    // ---- fp64 one-time covariance: r[k] = 0.5((k+1)^a + |k-1|^a - 2 k^a), tapered
    for (int k = tid; k < N; k += NT) {
        double kp = pow((double)(k + 1), a);
        double km = (k == 1) ? 0.0 : pow((double)(k >= 1 ? k - 1 : 1 - k), a);
        double k0 = (k == 0) ? 0.0 : pow((double)k, a);
        double R  = 0.5 * (kp + km - 2.0 * k0);
        if ((float)k >= tb) R *= exp(-LAM * (double)((float)k - tb));
        r[k] = (float)R;
    }
    const float* dub = du + (size_t)b * N * 3;
    for (int i = tid; i < N * 3; i += NT) zsh[i] = dub[i];
    __syncthreads();

    // replicated scalar state: identical ops on identical inputs -> bitwise equal
    float v = r[0];
    if (tid < 3) xh[tid * N] = sqrtf(v) * sd * zsh[tid];   // x_0 per dim
    __syncthreads();

    const float* x0 = xh;
    const float* x1 = xh + N;
    const float* x2 = xh + 2 * N;

    for (int n = 1; n < N; n++) {
        // ---- Phase A: 7 fused fp32 partial dots over k = 1..n-1 ----
        float p0 = 0.f, p1 = 0.f, p2 = 0.f, p3 = 0.f, p4 = 0.f, p5 = 0.f, p6 = 0.f;
        for (int k = tid + 1; k < n; k += NT) {
            float ph = phi[k];
            int m = n - k;
            p0 += ph * r[m];
            p1 += ph * x0[m];
            p2 += ph * x1[m];
            p3 += ph * x2[m];
            p4 += ph * x0[k];
            p5 += ph * x1[k];
            p6 += ph * x2[k];
        }
        #pragma unroll
        for (int o = 16; o > 0; o >>= 1) {
            p0 += __shfl_down_sync(0xffffffffu, p0, o);
            p1 += __shfl_down_sync(0xffffffffu, p1, o);
            p2 += __shfl_down_sync(0xffffffffu, p2, o);
            p3 += __shfl_down_sync(0xffffffffu, p3, o);
            p4 += __shfl_down_sync(0xffffffffu, p4, o);
            p5 += __shfl_down_sync(0xffffffffu, p5, o);
            p6 += __shfl_down_sync(0xffffffffu, p6, o);
        }
        if (lane == 0) {
            float* rw = red + warp * 8;
            rw[0] = p0; rw[1] = p1; rw[2] = p2; rw[3] = p3;
            rw[4] = p4; rw[5] = p5; rw[6] = p6;
        }
        __syncthreads();   // bar1: partials visible, phi/xh reads complete

        // ---- Phase B: replicated Durbin update (all threads, broadcast LDS) ----
        float s0 = ((red[0]      + red[8])      + (red[16]     + red[24]))
                 + ((red[32]     + red[40])     + (red[48]     + red[56]));
        float phinn = (r[n] - s0) / v;
        v *= (1.f - phinn * phinn);

        // threads 0..2: sample x_n for their dim (fully parallel, no shuffles)
        if (tid < 3) {
            int j = 1 + tid;
            float sA = ((red[j]      + red[8 + j])  + (red[16 + j] + red[24 + j]))
                     + ((red[32 + j] + red[40 + j]) + (red[48 + j] + red[56 + j]));
            int q = 4 + tid;
            float sB = ((red[q]      + red[8 + q])  + (red[16 + q] + red[24 + q]))
                     + ((red[32 + q] + red[40 + q]) + (red[48 + q] + red[56 + q]));
            float xn = sA - phinn * sB + phinn * xh[tid * N]
                     + sqrtf(v) * sd * zsh[n * 3 + tid];
            xh[tid * N + n] = xn;
        }
        if (tid == 0) phi[n] = phinn;

        // ---- Phase C: in-place pairwise phi update (local phinn, no broadcast) ----
        int half = n >> 1;
        for (int k = tid + 1; k <= half; k += NT) {
            int m = n - k;
            float pa = phi[k];
            if (m == k) {
                phi[k] = pa - phinn * pa;
            } else {
                float pb = phi[m];
                phi[k] = pa - phinn * pb;
                phi[m] = pb - phinn * pa;
            }
        }
        __syncthreads();   // bar2: phi + xh[n] visible for next iteration
    }

    // ---- post-loop: cumsum per dim, then coalesced output ----
    if (tid < 3) {
        float* xp = xh + tid * N;
        float c = 0.f;
        for (int i = 0; i < N; i++) { c += xp[i]; xp[i] = c; }
    }
    __syncthreads();

    float* ob = out + (size_t)b * T * 3;
    for (int i = tid; i < T * 3; i += NT) {
        int t = i / 3, d = i - 3 * t;
        ob[i] = (t == 0) ? 0.f : xh[d * N + (t - 1)];
    }
}

extern "C" void kernel_launch(void* const* d_in, const int* in_sizes, int n_in,
                              void* d_out, int out_size)
{
    const float* alpha = (const float*)d_in[0];
    const float* tau   = (const float*)d_in[1];
    const float* diffu = (const float*)d_in[2];
    const float* du    = (const float*)d_in[3];
    float* out = (float*)d_out;

    const int BS   = in_sizes[0];
    const int duN  = in_sizes[3] / BS;   // (T-1)*dim
    const int outN = out_size / BS;      // T*dim
    const int dim  = outN - duN;         // 3
    const int T    = outN / dim;
    const int N    = T - 1;

    size_t smem = (size_t)(N + (N + 1) + 3 * N + 64 + 3 * N) * sizeof(float);

    cudaFuncSetAttribute(fbm_hosking_f32,
                         cudaFuncAttributeMaxDynamicSharedMemorySize, (int)smem);

    fbm_hosking_f32<<<BS, NT, smem>>>(alpha, tau, diffu, du, out, T);
}

// round 4
// speedup vs baseline: 2.4490x; 2.4490x over previous
#include <cuda_runtime.h>
#include <math.h>

#define LAM 1.0
#define NT 256
#define SLOTS 4   // rows per thread (covers N up to 1024)

// Generator (Schur) algorithm for the Toeplitz Cholesky factor, fused with
// y = L @ (sqrt(D) * z) and cumsum. One CTA per batch.
//
// Displacement generators: u = r (since r[0] == 1 here), v = r with v[0]=0.
// Step n: rho = -v[n]/u0;  c = 1/sqrt(1-rho^2)
//   diagonal:  u0 <- c*(u0 + rho*v[n])            (register recursion)
//   for rows j>n:  (u[j-n], v[j]) <- hyperbolic rotation   (elementwise)
//   column n of L = rotated u  ->  y_d[j] += u_new * w_d[n] (registers)
// No dot products, no shuffles, 1 barrier per step.
__global__ __launch_bounds__(NT, 1)
void fbm_schur(const float* __restrict__ alpha,
               const float* __restrict__ tau,
               const float* __restrict__ diff,
               const float* __restrict__ du,
               float* __restrict__ out,
               int T)
{
    const int N = T - 1;                 // 1023
    extern __shared__ float sh[];
    float* u = sh;                       // [N]   generator 1 (sliding physical idx)
    float* v = u + N;                    // [N]   generator 2 (absolute idx)
    float* w = v + N;                    // [3*N] scaled noise; reused for dx2 later

    const int b   = blockIdx.x;
    const int tid = threadIdx.x;

    const double a  = (double)alpha[b];
    const float  tb = tau[b];
    const float  sd = sqrtf(diff[b]);

    // ---- autocovariance (fp64, one time): r[k] = 0.5((k+1)^a + |k-1|^a - 2k^a), taper
    for (int k = tid; k < N; k += NT) {
        double kp = pow((double)(k + 1), a);
        double km = (k == 1) ? 0.0 : pow((double)(k >= 1 ? k - 1 : 1 - k), a);
        double k0 = (k == 0) ? 0.0 : pow((double)k, a);
        double R  = 0.5 * (kp + km - 2.0 * k0);
        if ((float)k >= tb) R *= exp(-LAM * (double)((float)k - tb));
        float rf = (float)R;             // r[0] == 1 exactly
        u[k] = rf;
        v[k] = (k == 0) ? 0.f : rf;
    }
    const float* dub = du + (size_t)b * N * 3;
    for (int i = tid; i < N * 3; i += NT) w[i] = dub[i] * sd;
    __syncthreads();

    // ---- column 0: L[:,0] = r  ->  init register accumulators
    float y0[SLOTS], y1[SLOTS], y2[SLOTS];
    const float w00 = w[0], w01 = w[1], w02 = w[2];
    #pragma unroll
    for (int s = 0; s < SLOTS; s++) {
        int j = tid + NT * s;
        if (j < N) {
            float uj = u[j];
            y0[s] = uj * w00; y1[s] = uj * w01; y2[s] = uj * w02;
        } else { y0[s] = y1[s] = y2[s] = 0.f; }
    }
    __syncthreads();   // column-0 reads of u complete before step-1 writes

    // ---- main recursion: 1 barrier per step, all scalar state replicated
    float u0 = 1.0f;   // r[0]
    for (int n = 1; n < N; n++) {
        float vn  = v[n];                      // broadcast (written step n-1, never this step)
        float rho = -__fdividef(vn, u0);
        float t   = 1.f - rho * rho;
        float c   = rsqrtf(t);
        c = c * (1.5f - 0.5f * t * c * c);     // Newton refine to ~fp32 full precision
        float crho = c * rho;
        float u0n  = c * (u0 + rho * vn);      // new diagonal L[n,n]
        float wn0 = w[3 * n], wn1 = w[3 * n + 1], wn2 = w[3 * n + 2];

        #pragma unroll
        for (int s = 0; s < SLOTS; s++) {
            int j = tid + NT * s;
            if (j > n && j < N) {
                int   i  = j - n;              // sliding physical index into u
                float uu = u[i], vv = v[j];
                float un  = c * uu + crho * vv;
                float vnw = c * vv + crho * uu;
                u[i] = un; v[j] = vnw;
                y0[s] += un * wn0; y1[s] += un * wn1; y2[s] += un * wn2;
            } else if (j == n) {               // diagonal contribution
                y0[s] += u0n * wn0; y1[s] += u0n * wn1; y2[s] += u0n * wn2;
            }
        }
        u0 = u0n;
        __syncthreads();
    }

    // ---- dump dx registers to smem (reuse u, v, w[0:N]) ----
    #pragma unroll
    for (int s = 0; s < SLOTS; s++) {
        int j = tid + NT * s;
        if (j < N) { u[j] = y0[s]; v[j] = y1[s]; w[j] = y2[s]; }
    }
    __syncthreads();

    // ---- cumsum per dim: warp d scans dim d (chunked + warp scan) ----
    {
        int warp = tid >> 5, lane = tid & 31;
        if (warp < 3) {
            float* p = (warp == 0) ? u : ((warp == 1) ? v : w);
            int chunk = (N + 31) >> 5;
            int lo = lane * chunk;
            int hi = lo + chunk; if (hi > N) hi = N;
            float run = 0.f;
            for (int i = lo; i < hi; i++) { run += p[i]; p[i] = run; }
            float tot = run;
            #pragma unroll
            for (int o = 1; o < 32; o <<= 1) {
                float t2 = __shfl_up_sync(0xffffffffu, tot, o);
                if (lane >= o) tot += t2;
            }
            float off = tot - run;            // exclusive prefix of chunk sums
            for (int i = lo; i < hi; i++) p[i] += off;
        }
    }
    __syncthreads();

    // ---- output: leading zero row + interleaved dims, coalesced ----
    float* ob = out + (size_t)b * T * 3;
    for (int idx = tid; idx < T * 3; idx += NT) {
        int t = idx / 3, d = idx - 3 * t;
        float val = 0.f;
        if (t > 0) {
            int j = t - 1;
            val = (d == 0) ? u[j] : ((d == 1) ? v[j] : w[j]);
        }
        ob[idx] = val;
    }
}

extern "C" void kernel_launch(void* const* d_in, const int* in_sizes, int n_in,
                              void* d_out, int out_size)
{
    const float* alpha = (const float*)d_in[0];
    const float* tau   = (const float*)d_in[1];
    const float* diffu = (const float*)d_in[2];
    const float* du    = (const float*)d_in[3];
    float* out = (float*)d_out;

    const int BS   = in_sizes[0];
    const int duN  = in_sizes[3] / BS;   // (T-1)*dim
    const int outN = out_size / BS;      // T*dim
    const int dim  = outN - duN;         // 3
    const int T    = outN / dim;
    const int N    = T - 1;

    size_t smem = (size_t)(N + N + 3 * N) * sizeof(float);

    cudaFuncSetAttribute(fbm_schur,
                         cudaFuncAttributeMaxDynamicSharedMemorySize, (int)smem);

    fbm_schur<<<BS, NT, smem>>>(alpha, tau, diffu, du, out, T);
}

// round 5
// speedup vs baseline: 2.4563x; 1.0030x over previous
#include <cuda_runtime.h>
#include <math.h>

#define LAM 1.0
#define NT 256
#define SLOTS 4   // rows per thread (covers N up to 1024)

// Generator (Schur) algorithm for the Toeplitz Cholesky factor, fused with
// y = L @ (sqrt(D) * z) and cumsum. One CTA per batch.
//
// Displacement generators: u = r (since r[0] == 1 here), v = r with v[0]=0.
// Step n: rho = -v[n]/u0;  c = 1/sqrt(1-rho^2)
//   diagonal:  u0 <- c*(u0 + rho*v[n])            (register recursion)
//   for rows j>n:  (u[j-n], v[j]) <- hyperbolic rotation   (elementwise)
//   column n of L = rotated u  ->  y_d[j] += u_new * w_d[n] (registers)
// No dot products, no shuffles, 1 barrier per step.
__global__ __launch_bounds__(NT, 1)
void fbm_schur(const float* __restrict__ alpha,
               const float* __restrict__ tau,
               const float* __restrict__ diff,
               const float* __restrict__ du,
               float* __restrict__ out,
               int T)
{
    const int N = T - 1;                 // 1023
    extern __shared__ float sh[];
    float* u = sh;                       // [N]   generator 1 (sliding physical idx)
    float* v = u + N;                    // [N]   generator 2 (absolute idx)
    float* w = v + N;                    // [3*N] scaled noise; reused for dx2 later

    const int b   = blockIdx.x;
    const int tid = threadIdx.x;

    const double a  = (double)alpha[b];
    const float  tb = tau[b];
    const float  sd = sqrtf(diff[b]);

    // ---- autocovariance (fp64, one time): r[k] = 0.5((k+1)^a + |k-1|^a - 2k^a), taper
    for (int k = tid; k < N; k += NT) {
        double kp = pow((double)(k + 1), a);
        double km = (k == 1) ? 0.0 : pow((double)(k >= 1 ? k - 1 : 1 - k), a);
        double k0 = (k == 0) ? 0.0 : pow((double)k, a);
        double R  = 0.5 * (kp + km - 2.0 * k0);
        if ((float)k >= tb) R *= exp(-LAM * (double)((float)k - tb));
        float rf = (float)R;             // r[0] == 1 exactly
        u[k] = rf;
        v[k] = (k == 0) ? 0.f : rf;
    }
    const float* dub = du + (size_t)b * N * 3;
    for (int i = tid; i < N * 3; i += NT) w[i] = dub[i] * sd;
    __syncthreads();

    // ---- column 0: L[:,0] = r  ->  init register accumulators
    float y0[SLOTS], y1[SLOTS], y2[SLOTS];
    const float w00 = w[0], w01 = w[1], w02 = w[2];
    #pragma unroll
    for (int s = 0; s < SLOTS; s++) {
        int j = tid + NT * s;
        if (j < N) {
            float uj = u[j];
            y0[s] = uj * w00; y1[s] = uj * w01; y2[s] = uj * w02;
        } else { y0[s] = y1[s] = y2[s] = 0.f; }
    }
    __syncthreads();   // column-0 reads of u complete before step-1 writes

    // ---- main recursion: 1 barrier per step, all scalar state replicated
    float u0 = 1.0f;   // r[0]
    for (int n = 1; n < N; n++) {
        float vn  = v[n];                      // broadcast (written step n-1, never this step)
        float rho = -__fdividef(vn, u0);
        float t   = 1.f - rho * rho;
        float c   = rsqrtf(t);
        c = c * (1.5f - 0.5f * t * c * c);     // Newton refine to ~fp32 full precision
        float crho = c * rho;
        float u0n  = c * (u0 + rho * vn);      // new diagonal L[n,n]
        float wn0 = w[3 * n], wn1 = w[3 * n + 1], wn2 = w[3 * n + 2];

        #pragma unroll
        for (int s = 0; s < SLOTS; s++) {
            int j = tid + NT * s;
            if (j > n && j < N) {
                int   i  = j - n;              // sliding physical index into u
                float uu = u[i], vv = v[j];
                float un  = c * uu + crho * vv;
                float vnw = c * vv + crho * uu;
                u[i] = un; v[j] = vnw;
                y0[s] += un * wn0; y1[s] += un * wn1; y2[s] += un * wn2;
            } else if (j == n) {               // diagonal contribution
                y0[s] += u0n * wn0; y1[s] += u0n * wn1; y2[s] += u0n * wn2;
            }
        }
        u0 = u0n;
        __syncthreads();
    }

    // ---- dump dx registers to smem (reuse u, v, w[0:N]) ----
    #pragma unroll
    for (int s = 0; s < SLOTS; s++) {
        int j = tid + NT * s;
        if (j < N) { u[j] = y0[s]; v[j] = y1[s]; w[j] = y2[s]; }
    }
    __syncthreads();

    // ---- cumsum per dim: warp d scans dim d (chunked + warp scan) ----
    {
        int warp = tid >> 5, lane = tid & 31;
        if (warp < 3) {
            float* p = (warp == 0) ? u : ((warp == 1) ? v : w);
            int chunk = (N + 31) >> 5;
            int lo = lane * chunk;
            int hi = lo + chunk; if (hi > N) hi = N;
            float run = 0.f;
            for (int i = lo; i < hi; i++) { run += p[i]; p[i] = run; }
            float tot = run;
            #pragma unroll
            for (int o = 1; o < 32; o <<= 1) {
                float t2 = __shfl_up_sync(0xffffffffu, tot, o);
                if (lane >= o) tot += t2;
            }
            float off = tot - run;            // exclusive prefix of chunk sums
            for (int i = lo; i < hi; i++) p[i] += off;
        }
    }
    __syncthreads();

    // ---- output: leading zero row + interleaved dims, coalesced ----
    float* ob = out + (size_t)b * T * 3;
    for (int idx = tid; idx < T * 3; idx += NT) {
        int t = idx / 3, d = idx - 3 * t;
        float val = 0.f;
        if (t > 0) {
            int j = t - 1;
            val = (d == 0) ? u[j] : ((d == 1) ? v[j] : w[j]);
        }
        ob[idx] = val;
    }
}

extern "C" void kernel_launch(void* const* d_in, const int* in_sizes, int n_in,
                              void* d_out, int out_size)
{
    const float* alpha = (const float*)d_in[0];
    const float* tau   = (const float*)d_in[1];
    const float* diffu = (const float*)d_in[2];
    const float* du    = (const float*)d_in[3];
    float* out = (float*)d_out;

    const int BS   = in_sizes[0];
    const int duN  = in_sizes[3] / BS;   // (T-1)*dim
    const int outN = out_size / BS;      // T*dim
    const int dim  = outN - duN;         // 3
    const int T    = outN / dim;
    const int N    = T - 1;

    size_t smem = (size_t)(N + N + 3 * N) * sizeof(float);

    cudaFuncSetAttribute(fbm_schur,
                         cudaFuncAttributeMaxDynamicSharedMemorySize, (int)smem);

    fbm_schur<<<BS, NT, smem>>>(alpha, tau, diffu, du, out, T);
}